// round 17
// baseline (speedup 1.0000x reference)
#include <cuda_runtime.h>
#include <cuda_bf16.h>
#include <cstdint>
#include <cstddef>

#define FULLMASK 0xffffffffu
#define B_ROWS 65536
#define D_INN 1408
#define P_DIM 256
#define N_CODE 64
#define KCH 32
#define NCH 44
#define NTHREADS 512

#define IDX_OFF  ((size_t)B_ROWS * P_DIM)
#define LOSS_OFF (IDX_OFF + B_ROWS)

// ---- smem byte offsets ----
#define SB_BIAS  0
#define SB_GAM   1024
#define SB_BET   2048
#define SB_NRM   3072      // float[128]
#define SB_ZZ    3584      // float[128]
#define SB_LOSSS 4096
#define UOFF     5120
#define APL(p)   (UOFF + (p) * 8192)     // A planes (single buf) 16KB total
// epilogue overlays (HBUF overlaps APL; CBT beyond BOTH, lives whole kernel)
#define HBUF     UOFF
#define HSTRIDE  260
#define CBT      (UOFF + 133120)
#define SMEM_BYTES (UOFF + 198656)       // 203776 — covers CBT (fix for R14 OOB)

// W in fragment order: uint4 per (chunk, khalf, ntile, lane) =
// {plane0 b0, plane0 b1, plane1 b0, plane1 b1}
__device__ uint4 g_wfrag[NCH * 2 * 32 * 32];
__device__ float g_cbn2[N_CODE];

static __device__ __forceinline__ unsigned smaddr(const void* p) {
    unsigned a;
    asm("{ .reg .u64 t; cvta.to.shared.u64 t, %1; cvt.u32.u64 %0, t; }" : "=r"(a) : "l"(p));
    return a;
}
static __device__ __forceinline__ float wred(float v) {
    #pragma unroll
    for (int o = 16; o; o >>= 1) v += __shfl_xor_sync(FULLMASK, v, o);
    return v;
}
static __device__ __forceinline__ unsigned packbf(float lo, float hi) {
    return (unsigned)__bfloat16_as_ushort(__float2bfloat16_rn(lo)) |
           ((unsigned)__bfloat16_as_ushort(__float2bfloat16_rn(hi)) << 16);
}

#define LDSM4(d0, d1, d2, d3, addr) \
    asm volatile("ldmatrix.sync.aligned.m8n8.x4.shared.b16 {%0,%1,%2,%3}, [%4];" \
                 : "=r"(d0), "=r"(d1), "=r"(d2), "=r"(d3) : "r"(addr))

#define MMA16816(c, a, b0, b1) \
    asm volatile("mma.sync.aligned.m16n8k16.row.col.f32.bf16.bf16.f32 " \
                 "{%0,%1,%2,%3},{%4,%5,%6,%7},{%8,%9},{%0,%1,%2,%3};" \
                 : "+f"((c)[0]), "+f"((c)[1]), "+f"((c)[2]), "+f"((c)[3]) \
                 : "r"((a)[0]), "r"((a)[1]), "r"((a)[2]), "r"((a)[3]), "r"(b0), "r"(b1))

// ---- init: W -> fragment-ordered split planes ----
// b0 lane l: {W[k0+0][n], W[k0+1][n]}, k0 = kh*16 + (l&3)*2, n = ntg*8 + (l>>2)
// b1: same with k0+8.
__global__ void init_w_kernel(const float* __restrict__ Wm) {
    int c = blockIdx.x >> 3, sub = blockIdx.x & 7;
    int kh = sub & 1, ntb = sub >> 1;
    int lane = threadIdx.x & 31, ntl = threadIdx.x >> 5;
    int ntg = ntb * 8 + ntl;
    int n = ntg * 8 + (lane >> 2);
    int k = c * KCH + kh * 16 + (lane & 3) * 2;
    float w00 = Wm[(size_t)k * P_DIM + n];
    float w01 = Wm[(size_t)(k + 1) * P_DIM + n];
    float w10 = Wm[(size_t)(k + 8) * P_DIM + n];
    float w11 = Wm[(size_t)(k + 9) * P_DIM + n];
    float h00 = __bfloat162float(__float2bfloat16_rn(w00));
    float h01 = __bfloat162float(__float2bfloat16_rn(w01));
    float h10 = __bfloat162float(__float2bfloat16_rn(w10));
    float h11 = __bfloat162float(__float2bfloat16_rn(w11));
    uint4 v;
    v.x = packbf(h00, h01);
    v.y = packbf(h10, h11);
    v.z = packbf(w00 - h00, w01 - h01);
    v.w = packbf(w10 - h10, w11 - h11);
    g_wfrag[(((c * 2 + kh) * 32 + ntg) << 5) + lane] = v;
}

__global__ void init_misc_kernel(const float* __restrict__ cb, float* __restrict__ out, int out_size) {
    int k = threadIdx.x;
    if (k < N_CODE) {
        const float* r = cb + k * P_DIM;
        double s = 0.0;
        #pragma unroll 8
        for (int c = 0; c < P_DIM; ++c) { double v = (double)r[c]; s += v * v; }
        g_cbn2[k] = (float)s;
    }
    if (k == 0 && (size_t)out_size > LOSS_OFF) out[LOSS_OFF] = 0.f;
}

__global__ void __launch_bounds__(NTHREADS, 1)
main_kernel(const float* __restrict__ zf, const float* __restrict__ bb,
            const float* __restrict__ gg, const float* __restrict__ be,
            const float* __restrict__ cb, float* __restrict__ out, int out_size) {
    extern __shared__ char smem[];
    const int tid = threadIdx.x;
    const int lane = tid & 31;
    const int wid = tid >> 5;          // 0..15
    const int wrr = wid >> 3;          // 0..1  (64-row group)
    const int wcc = wid & 7;           // 0..7  (32-col group)
    const int rowbase = blockIdx.x * 128;
    const bool aux = (size_t)out_size > LOSS_OFF;
    const unsigned sbase = smaddr(smem);
    float* smf = (float*)smem;

    // A-register mapping: thread owns row arow, k-segment aseg (8 floats/chunk)
    const int arow = tid >> 2;
    const int aseg = tid & 3;
    const float* arow_ptr = zf + (size_t)(rowbase + arow) * D_INN + aseg * 8;
    const int atile = (arow >> 3) * 4 + aseg;
    const unsigned aoff = atile * 128 + (((arow & 7) ^ (atile & 7)) << 4);

    // ---- prologue: A chunk 0 + B fragments chunk 0 into regs ----
    float4 a0 = *(const float4*)arow_ptr;
    float4 a1 = *(const float4*)(arow_ptr + 4);
    uint4 bq[2][4], bnx[2][4];
    #pragma unroll
    for (int kh = 0; kh < 2; ++kh)
        #pragma unroll
        for (int j = 0; j < 4; ++j)
            bq[kh][j] = g_wfrag[((kh * 32 + wcc * 4 + j) << 5) + lane];

    // ---- params, loss, cbt ----
    if (tid < P_DIM) {
        smf[SB_BIAS / 4 + tid] = bb[tid];
        smf[SB_GAM  / 4 + tid] = gg[tid];
        smf[SB_BET  / 4 + tid] = be[tid];
    }
    if (tid == 0) smf[SB_LOSSS / 4] = 0.f;
    float* cbt = (float*)(smem + CBT);
    #pragma unroll
    for (int t = 0; t < (N_CODE * P_DIM) / NTHREADS; ++t) {
        int i = tid + t * NTHREADS;
        int k = i >> 8, cc = i & 255;
        cbt[cc * N_CODE + k] = cb[i];
    }

    // ---- GEMM: 128x256/CTA, 16 warps, warp tile 64x32, 3-term split ----
    float acc[4][4][4];
    #pragma unroll
    for (int mt = 0; mt < 4; ++mt)
        #pragma unroll
        for (int nt = 0; nt < 4; ++nt)
            #pragma unroll
            for (int e = 0; e < 4; ++e) acc[mt][nt][e] = 0.f;
    float nacc = 0.f;

    for (int c = 0; c < NCH; ++c) {
        // orders chunk-(c-1) MMA ldmatrix reads of APL before new stores
        __syncthreads();
        if (c + 1 < NCH) {
            #pragma unroll
            for (int kh = 0; kh < 2; ++kh)
                #pragma unroll
                for (int j = 0; j < 4; ++j)
                    bnx[kh][j] = g_wfrag[((((c + 1) * 2 + kh) * 32 + wcc * 4 + j) << 5) + lane];
        }

        // convert A regs -> 2 bf16 planes; accumulate row norms
        {
            float vv[8] = {a0.x, a0.y, a0.z, a0.w, a1.x, a1.y, a1.z, a1.w};
            __align__(16) __nv_bfloat16 h8[8], m8[8];
            #pragma unroll
            for (int j = 0; j < 8; ++j) {
                nacc += vv[j] * vv[j];
                __nv_bfloat16 h = __float2bfloat16_rn(vv[j]);
                __nv_bfloat16 m = __float2bfloat16_rn(vv[j] - __bfloat162float(h));
                h8[j] = h; m8[j] = m;
            }
            *(uint4*)(smem + APL(0) + aoff) = *(uint4*)h8;
            *(uint4*)(smem + APL(1) + aoff) = *(uint4*)m8;
        }
        if (c + 1 < NCH) {
            const float* p = arow_ptr + (c + 1) * KCH;
            a0 = *(const float4*)p;
            a1 = *(const float4*)(p + 4);
        }
        __syncthreads();

        // MMA: terms A0*B0, A0*B1, A1*B0
        const int i4 = lane >> 3;
        #pragma unroll
        for (int s = 0; s < 2; ++s) {
            const int kb0 = 2 * s;
            unsigned afr[16];
            #pragma unroll
            for (int mt = 0; mt < 4; ++mt) {
                int rb = wrr * 8 + mt * 2 + (i4 & 1);
                int kb = kb0 + (i4 >> 1);
                int tile = rb * 4 + kb;
                unsigned addr = sbase + APL(0) + tile * 128 + (((lane & 7) ^ (tile & 7)) << 4);
                LDSM4(afr[mt * 4 + 0], afr[mt * 4 + 1], afr[mt * 4 + 2], afr[mt * 4 + 3], addr);
            }
            #pragma unroll
            for (int mt = 0; mt < 4; ++mt)
                #pragma unroll
                for (int nt = 0; nt < 4; ++nt) {
                    MMA16816(acc[mt][nt], &afr[mt * 4], bq[s][nt].x, bq[s][nt].y);
                    MMA16816(acc[mt][nt], &afr[mt * 4], bq[s][nt].z, bq[s][nt].w);
                }
            #pragma unroll
            for (int mt = 0; mt < 4; ++mt) {
                int rb = wrr * 8 + mt * 2 + (i4 & 1);
                int kb = kb0 + (i4 >> 1);
                int tile = rb * 4 + kb;
                unsigned addr = sbase + APL(1) + tile * 128 + (((lane & 7) ^ (tile & 7)) << 4);
                LDSM4(afr[mt * 4 + 0], afr[mt * 4 + 1], afr[mt * 4 + 2], afr[mt * 4 + 3], addr);
            }
            #pragma unroll
            for (int mt = 0; mt < 4; ++mt)
                #pragma unroll
                for (int nt = 0; nt < 4; ++nt)
                    MMA16816(acc[mt][nt], &afr[mt * 4], bq[s][nt].x, bq[s][nt].y);
        }
        #pragma unroll
        for (int kh = 0; kh < 2; ++kh)
            #pragma unroll
            for (int j = 0; j < 4; ++j) bq[kh][j] = bnx[kh][j];
    }

    // ---- finalize row norms (4 threads per row) ----
    nacc += __shfl_xor_sync(FULLMASK, nacc, 1);
    nacc += __shfl_xor_sync(FULLMASK, nacc, 2);
    if (aseg == 0) smf[SB_NRM / 4 + arow] = nacc;
    __syncthreads();   // GEMM reads done; HBUF overlay writable; norms visible

    // ---- h writeback: h = acc/||x|| + b ----
    float* hbuf = (float*)(smem + HBUF);
    #pragma unroll
    for (int mt = 0; mt < 4; ++mt) {
        int r1 = wrr * 64 + mt * 16 + (lane >> 2);
        int r2 = r1 + 8;
        float invn1 = 1.0f / fmaxf(sqrtf(smf[SB_NRM / 4 + r1]), 1e-12f);
        float invn2 = 1.0f / fmaxf(sqrtf(smf[SB_NRM / 4 + r2]), 1e-12f);
        #pragma unroll
        for (int nt = 0; nt < 4; ++nt) {
            int c0 = wcc * 32 + nt * 8 + 2 * (lane & 3);
            float2 o1 = make_float2(acc[mt][nt][0] * invn1 + smf[SB_BIAS / 4 + c0],
                                    acc[mt][nt][1] * invn1 + smf[SB_BIAS / 4 + c0 + 1]);
            float2 o2 = make_float2(acc[mt][nt][2] * invn2 + smf[SB_BIAS / 4 + c0],
                                    acc[mt][nt][3] * invn2 + smf[SB_BIAS / 4 + c0 + 1]);
            *(float2*)&hbuf[r1 * HSTRIDE + c0] = o1;
            *(float2*)&hbuf[r2 * HSTRIDE + c0] = o2;
        }
    }
    __syncthreads();

    // ---- LayerNorm + l2norm per row (16 warps x 8 rows) ----
    const int tn = lane;
    #pragma unroll
    for (int i = 0; i < 8; ++i) {
        int lrow = wid + 16 * i;
        float hv[8];
        #pragma unroll
        for (int jp = 0; jp < 4; ++jp) {
            int c0 = 2 * tn + 64 * jp;
            float2 v = *(const float2*)&hbuf[lrow * HSTRIDE + c0];
            hv[2 * jp] = v.x; hv[2 * jp + 1] = v.y;
        }
        float s1 = 0.f;
        #pragma unroll
        for (int j = 0; j < 8; ++j) s1 += hv[j];
        s1 = wred(s1);
        float mu = s1 * (1.0f / 256.0f);
        float s2 = 0.f;
        #pragma unroll
        for (int j = 0; j < 8; ++j) { float d = hv[j] - mu; s2 += d * d; }
        s2 = wred(s2);
        float rstd = 1.0f / sqrtf(s2 * (1.0f / 256.0f) + 1e-5f);
        float zp[8];
        #pragma unroll
        for (int jp = 0; jp < 4; ++jp) {
            int c0 = 2 * tn + 64 * jp;
            zp[2 * jp]     = (hv[2 * jp] - mu) * rstd * smf[SB_GAM / 4 + c0] + smf[SB_BET / 4 + c0];
            zp[2 * jp + 1] = (hv[2 * jp + 1] - mu) * rstd * smf[SB_GAM / 4 + c0 + 1] + smf[SB_BET / 4 + c0 + 1];
        }
        float s3 = 0.f;
        #pragma unroll
        for (int j = 0; j < 8; ++j) s3 += zp[j] * zp[j];
        s3 = wred(s3);
        float zn = fmaxf(sqrtf(s3), 1e-12f);
        float szz = 0.f;
        #pragma unroll
        for (int jp = 0; jp < 4; ++jp) {
            int c0 = 2 * tn + 64 * jp;
            float2 zv = make_float2(zp[2 * jp] / zn, zp[2 * jp + 1] / zn);
            szz += zv.x * zv.x + zv.y * zv.y;
            *(float2*)&hbuf[lrow * HSTRIDE + c0] = zv;
        }
        szz = wred(szz);
        if (tn == 0) smf[SB_ZZ / 4 + lrow] = szz;
    }
    __syncthreads();

    // ---- codebook dots + argmin + outputs (16 warps x 8 rows) ----
    float cn0 = g_cbn2[2 * tn];
    float cn1 = g_cbn2[2 * tn + 1];
    float lpart = 0.f;
    {
        float dq[4][8][2];
        #pragma unroll
        for (int q = 0; q < 4; ++q)
            #pragma unroll
            for (int i = 0; i < 8; ++i) { dq[q][i][0] = 0.f; dq[q][i][1] = 0.f; }
        #pragma unroll 2
        for (int kb = 0; kb < P_DIM / 4; ++kb) {
            float4 za[8];
            #pragma unroll
            for (int i = 0; i < 8; ++i)
                za[i] = *(const float4*)&hbuf[(wid + 16 * i) * HSTRIDE + kb * 4];
            #pragma unroll
            for (int q = 0; q < 4; ++q) {
                float2 cw = *(const float2*)&cbt[(kb * 4 + q) * N_CODE + 2 * tn];
                #pragma unroll
                for (int i = 0; i < 8; ++i) {
                    float zv = ((const float*)&za[i])[q];
                    dq[q][i][0] += zv * cw.x;
                    dq[q][i][1] += zv * cw.y;
                }
            }
        }
        #pragma unroll
        for (int i = 0; i < 8; ++i) {
            float dot0 = __fadd_rn(__fadd_rn(dq[0][i][0], dq[1][i][0]),
                                   __fadd_rn(dq[2][i][0], dq[3][i][0]));
            float dot1 = __fadd_rn(__fadd_rn(dq[0][i][1], dq[1][i][1]),
                                   __fadd_rn(dq[2][i][1], dq[3][i][1]));
            int lrow = wid + 16 * i;
            float zz = smf[SB_ZZ / 4 + lrow];
            float d0 = __fadd_rn(__fsub_rn(zz, 2.0f * dot0), cn0);
            float d1 = __fadd_rn(__fsub_rn(zz, 2.0f * dot1), cn1);
            float bd = d0; int bk = 2 * tn;
            if (d1 < bd) { bd = d1; bk = 2 * tn + 1; }
            #pragma unroll
            for (int o = 16; o; o >>= 1) {
                float od = __shfl_xor_sync(FULLMASK, bd, o);
                int   ok = __shfl_xor_sync(FULLMASK, bk, o);
                if (od < bd || (od == bd && ok < bk)) { bd = od; bk = ok; }
            }
            int grow = rowbase + lrow;
            const float* cbr = cb + bk * P_DIM;
            #pragma unroll
            for (int jp = 0; jp < 4; ++jp) {
                int c0 = 2 * tn + 64 * jp;
                float2 cv = *(const float2*)&cbr[c0];
                float2 zz2 = *(const float2*)&hbuf[lrow * HSTRIDE + c0];
                float e0 = cv.x - zz2.x, e1 = cv.y - zz2.y;
                lpart += e0 * e0 + e1 * e1;
                *(float2*)&out[(size_t)grow * P_DIM + c0] = cv;
            }
            if (tn == 0 && aux) out[IDX_OFF + grow] = (float)bk;
        }
    }
    lpart = wred(lpart);
    if (tn == 0) atomicAdd(&smf[SB_LOSSS / 4], lpart);
    __syncthreads();
    if (tid == 0 && aux)
        atomicAdd(&out[LOSS_OFF], smf[SB_LOSSS / 4] * (0.25f / 16777216.0f));
}

extern "C" void kernel_launch(void* const* d_in, const int* in_sizes, int n_in,
                              void* d_out, int out_size) {
    const float* zf = (const float*)d_in[0];
    const float* Wm = (const float*)d_in[1];
    const float* bb = (const float*)d_in[2];
    const float* gg = (const float*)d_in[3];
    const float* be = (const float*)d_in[4];
    const float* cb = (const float*)d_in[5];
    float* out = (float*)d_out;

    cudaFuncSetAttribute(main_kernel, cudaFuncAttributeMaxDynamicSharedMemorySize, SMEM_BYTES);
    init_w_kernel<<<NCH * 8, P_DIM>>>(Wm);
    init_misc_kernel<<<1, 64>>>(cb, out, out_size);
    main_kernel<<<B_ROWS / 128, NTHREADS, SMEM_BYTES>>>(zf, bb, gg, be, cb, out, out_size);
}